// round 15
// baseline (speedup 1.0000x reference)
#include <cuda_runtime.h>
#include <math.h>

#define YDIM  25
#define NPATH 4864
#define OUTD  144
#define DTOT  259
#define SRTOT 3584   // staged R floats per z (bij 4,5,7,8 only)

// runtime-indexed metadata (used in D-build phase)
__constant__ int c_NLF[9]   = {1,1,1,1,3,3,1,3,5};
__constant__ int c_DBASE[9] = {0,1,4,9,12,39,84,89,134};
__constant__ int c_LF0[9]   = {0,1,2,1,0,1,2,1,0};
__constant__ int c_CGB[9][5] = {
    {0,0,0,0,0},{1,0,0,0,0},{10,0,0,0,0},{35,0,0,0,0},
    {44,53,80,0,0},{125,170,245,0,0},{350,0,0,0,0},
    {375,420,495,0,0},{600,625,700,825,1000}};
__constant__ int c_YOFF[5]  = {0,1,4,9,16};

// compile-time metadata
__host__ __device__ constexpr int K_ROFF[9]  = {0,256,512,768,1024,1792,2560,2816,3584};
__host__ __device__ constexpr int K_DBASE[9] = {0,1,4,9,12,39,84,89,134};
// smem float offsets for staged bij blocks (4,5,7,8); others unstaged (LDG16)
__host__ __device__ constexpr int K_SOFF[9]  = {-1,-1,-1,-1,0,768,-1,1536,2304};

// ---------------------------------------------------------------------------
// Compile-time CG table (constexpr fp64 Wigner-3j + basis transform)
// ---------------------------------------------------------------------------
struct CGTable { float v[1225]; };
struct CCd { double re, im; };

constexpr double cfact(int n) { double f = 1.0; for (int i = 2; i <= n; ++i) f *= (double)i; return f; }

constexpr double csqrt_(double x) {
    if (x <= 0.0) return 0.0;
    double g = (x > 1.0) ? x : 1.0;
    for (int i = 0; i < 80; ++i) g = 0.5 * (g + x / g);
    return g;
}

constexpr double cw3j(int j1, int j2, int j3, int m1, int m2, int m3) {
    if (m1 + m2 + m3 != 0) return 0.0;
    int dj = (j1 > j2) ? (j1 - j2) : (j2 - j1);
    if (j3 < dj || j3 > j1 + j2) return 0.0;
    int am1 = m1 < 0 ? -m1 : m1, am2 = m2 < 0 ? -m2 : m2, am3 = m3 < 0 ? -m3 : m3;
    if (am1 > j1 || am2 > j2 || am3 > j3) return 0.0;
    double pre = csqrt_(cfact(j1+j2-j3)*cfact(j1-j2+j3)*cfact(-j1+j2+j3)/cfact(j1+j2+j3+1));
    pre *= csqrt_(cfact(j1+m1)*cfact(j1-m1)*cfact(j2+m2)*cfact(j2-m2)*cfact(j3+m3)*cfact(j3-m3));
    int t0 = 0;
    if (j2 - j3 - m1 > t0) t0 = j2 - j3 - m1;
    if (j1 - j3 + m2 > t0) t0 = j1 - j3 + m2;
    int t1 = j1 + j2 - j3;
    if (j1 - m1 < t1) t1 = j1 - m1;
    if (j2 + m2 < t1) t1 = j2 + m2;
    double s = 0.0;
    for (int t = t0; t <= t1; ++t) {
        double d = cfact(t)*cfact(j3-j2+m1+t)*cfact(j3-j1-m2+t)
                 * cfact(j1+j2-j3-t)*cfact(j1-m1-t)*cfact(j2+m2-t);
        s += ((t & 1) ? -1.0 : 1.0) / d;
    }
    int p = j1 - j2 - m3;
    double sg = (p & 1) ? -1.0 : 1.0;
    return sg * pre * s;
}

constexpr CCd aent(int l, int r, int c) {
    CCd o{0.0, 0.0};
    int M = r - l, m = c - l;
    double s2 = csqrt_(0.5);
    if (M > 0) {
        double sg = (M & 1) ? -s2 : s2;
        if (m == M)       o.re = sg;
        else if (m == -M) o.im = sg;
    } else if (M < 0) {
        if (m == -M)      o.re = s2;
        else if (m == M)  o.im = -s2;
    } else {
        if (m == 0) o.re = 1.0;
    }
    return o;
}

constexpr CGTable makeCG() {
    CGTable T{};
    int CGB[9][5] = {
        {0,0,0,0,0},{1,0,0,0,0},{10,0,0,0,0},{35,0,0,0,0},
        {44,53,80,0,0},{125,170,245,0,0},{350,0,0,0,0},
        {375,420,495,0,0},{600,625,700,825,1000}};
    for (int bij = 0; bij < 9; ++bij) {
        int l1 = bij / 3, l2 = bij % 3;
        int dl = (l1 > l2) ? (l1 - l2) : (l2 - l1);
        int nk = 2 * ((l1 < l2) ? l1 : l2) + 1;
        for (int k = 0; k < nk; ++k) {
            int l3 = dl + k;
            int n1 = 2*l1+1, n2 = 2*l2+1, n3 = 2*l3+1;
            double Cre[225] = {}, Cim[225] = {};
            for (int m1 = -l1; m1 <= l1; ++m1)
                for (int m2 = -l2; m2 <= l2; ++m2) {
                    int m3 = -(m1 + m2);
                    if (m3 < -l3 || m3 > l3) continue;
                    double w = cw3j(l1, l2, l3, m1, m2, m3);
                    if (w == 0.0) continue;
                    for (int i = 0; i < n1; ++i) {
                        CCd a1 = aent(l1, m1 + l1, i); a1.im = -a1.im;
                        for (int j = 0; j < n2; ++j) {
                            CCd a2 = aent(l2, m2 + l2, j); a2.im = -a2.im;
                            double pr = a1.re*a2.re - a1.im*a2.im;
                            double pi = a1.re*a2.im + a1.im*a2.re;
                            for (int kk = 0; kk < n3; ++kk) {
                                CCd a3 = aent(l3, m3 + l3, kk); a3.im = -a3.im;
                                double qr = pr*a3.re - pi*a3.im;
                                double qi = pr*a3.im + pi*a3.re;
                                int x = (i*n2 + j)*n3 + kk;
                                Cre[x] += w * qr;
                                Cim[x] += w * qi;
                            }
                        }
                    }
                }
            int tot = n1 * n2 * n3;
            double nr = 0.0, ni = 0.0;
            for (int x = 0; x < tot; ++x) { nr += Cre[x]*Cre[x]; ni += Cim[x]*Cim[x]; }
            bool useRe = (nr >= ni);
            double nn = csqrt_(useRe ? nr : ni);
            int base = CGB[bij][k];
            for (int x = 0; x < tot; ++x) {
                double vl = useRe ? Cre[x] : Cim[x];
                T.v[base + x] = (float)((nn > 0.0) ? vl / nn : 0.0);
            }
        }
    }
    return T;
}

constexpr CGTable CGT = makeCG();
__device__ const CGTable d_CGT = CGT;

// ---------------------------------------------------------------------------
// Main kernel. 288 threads = 2 z; warp-pure j mapping; single-column ownership.
// NLF=1 sub-blocks (bij 0,1,2,3,6): batched MLP=16 LDG prefetch into registers
// then pure stores. NLF>1 sub-blocks (bij 4,5,7,8): smem-staged, D hoisted to
// registers with NIO=5 split into io-chunks of 3+2 (worst-path hoist 15 regs).
// u-loops fully unrolled: all addressing folds to immediate offsets.
// smem ~30KB + regs<=32 -> 7 blocks/SM = 63 warps (1 below the 64-warp cap).
// ---------------------------------------------------------------------------
template<int NC_, int NSTRIDE, int NLF, int NJI>
__device__ __forceinline__ void do_iblock(const float* __restrict__ Sg, int rb,
                                          const float* __restrict__ dpb,
                                          float* __restrict__ op)
{
    float D[NC_ * NLF];
    #pragma unroll
    for (int io = 0; io < NC_; io++)
        #pragma unroll
        for (int k = 0; k < NLF; k++)
            D[io*NLF + k] = dpb[io * (NJI*NLF) + k];

    #pragma unroll
    for (int u = 0; u < 16; u++) {
        float rv[NLF];
        #pragma unroll
        for (int k = 0; k < NLF; k++) rv[k] = Sg[rb + u*16*NLF + k];
        float* o = op + (size_t)(u * NSTRIDE) * OUTD;
        #pragma unroll
        for (int io = 0; io < NC_; io++) {
            float acc = 0.f;
            #pragma unroll
            for (int k = 0; k < NLF; k++) acc = fmaf(D[io*NLF + k], rv[k], acc);
            __stcs(o, acc);
            o += OUTD;
        }
    }
}

// NLF=1 path: prefetch all 16 R scalars (independent LDGs), then pure stores.
template<int NIO, int NJI>
__device__ __forceinline__ void iblk_ldg16(const float* __restrict__ rp,
                                           const float* __restrict__ dpb,
                                           float* __restrict__ op)
{
    float rv[16];
    #pragma unroll
    for (int u = 0; u < 16; u++) rv[u] = __ldg(rp + u*16);
    float D[NIO];
    #pragma unroll
    for (int io = 0; io < NIO; io++) D[io] = dpb[io*NJI];
    #pragma unroll
    for (int u = 0; u < 16; u++) {
        float* o = op + (size_t)(u * NIO) * OUTD;
        #pragma unroll
        for (int io = 0; io < NIO; io++) {
            __stcs(o, D[io] * rv[u]);
            o += OUTD;
        }
    }
}

template<int LJ>
__device__ __forceinline__ void compute_cols(const float* __restrict__ Rz,
                                             const float* __restrict__ Sg,
                                             const float* __restrict__ Dg,
                                             float* __restrict__ op,
                                             int v, int jo)
{
    constexpr int NJI = 2*LJ + 1;
    // i = 0  (bij = LJ, NLF = 1, unstaged -> LDG16 prefetch)
    iblk_ldg16<1, NJI>(Rz + K_ROFF[LJ] + v, Dg + K_DBASE[LJ] + jo, op);
    // i = 1  (bij = 3+LJ, NIO = 3, staged, NLF = 3)
    do_iblock<3, 3, 3, NJI>(Sg, K_SOFF[3+LJ] + v*3,
                            Dg + K_DBASE[3+LJ] + jo*3, op + 16*OUTD);
    // i = 2  (bij = 6+LJ, NIO = 5, staged) -> io-chunks 3 + 2
    {
        constexpr int NLF = (LJ == 1) ? 3 : 5;
        const float* dpb = Dg + K_DBASE[6+LJ] + jo*NLF;
        const int rb = K_SOFF[6+LJ] + v*NLF;
        do_iblock<3, 5, NLF, NJI>(Sg, rb, dpb, op + 64*OUTD);
        do_iblock<2, 5, NLF, NJI>(Sg, rb, dpb + 3*(NJI*NLF),
                                  op + 64*OUTD + 3*OUTD);
    }
}

__device__ __forceinline__ void compute_cols0(const float* __restrict__ Rz,
                                              const float* __restrict__ Dg,
                                              float* __restrict__ op, int v)
{
    iblk_ldg16<1, 1>(Rz + K_ROFF[0] + v, Dg + K_DBASE[0], op);
    iblk_ldg16<3, 1>(Rz + K_ROFF[3] + v, Dg + K_DBASE[3], op + 16*OUTD);
    iblk_ldg16<5, 1>(Rz + K_ROFF[6] + v, Dg + K_DBASE[6], op + 64*OUTD);
}

__global__ __launch_bounds__(288, 7)
void tp_kernel(const float* __restrict__ Y, const float* __restrict__ R,
               const float* __restrict__ NC, float* __restrict__ out, int batch)
{
    __shared__ float Rsh[2][SRTOT];
    __shared__ float Ysh[2][YDIM];
    __shared__ float Nsh[2][9];
    __shared__ float Dsh[2][DTOT];

    const int tid = threadIdx.x;
    const int gf = tid / 144;
    const int cf = tid - gf * 144;

    // stage bij {4,5} and {7,8} R segments -> smem, 16B vectors, streaming
    {
        const int zf = blockIdx.x * 2 + gf;
        const float4* Rz4 = (const float4*)(R + (size_t)zf * NPATH);
        float4* S4 = (float4*)Rsh[gf];
        // floats [1024,2560) -> 0 ; [2816,4864) -> 1536
        for (int idx = cf; idx < 384; idx += 144) S4[idx]       = __ldcs(Rz4 + 256 + idx);
        for (int idx = cf; idx < 512; idx += 144) S4[384 + idx] = __ldcs(Rz4 + 704 + idx);
        if (cf < YDIM) Ysh[gf][cf] = Y[cf * batch + zf];
        if (cf < 9)    Nsh[gf][cf] = NC[cf * batch + zf];
    }
    __syncthreads();

    // D[e] = norm[bij] * sum_m CG[bij,k][pair][m] * Y[yoff+m]   (259 entries)
    for (int e = cf; e < DTOT; e += 144) {
        int bij = (e>=134)?8:(e>=89)?7:(e>=84)?6:(e>=39)?5:(e>=12)?4:(e>=9)?3:(e>=4)?2:(e>=1)?1:0;
        int local = e - c_DBASE[bij];
        int nlf = c_NLF[bij];
        int k = local % nlf;
        int pair = local / nlf;
        int lf = c_LF0[bij] + k;
        int nm = 2*lf + 1;
        const float* cg = d_CGT.v + c_CGB[bij][k] + pair * nm;
        const float* y  = Ysh[gf] + c_YOFF[lf];
        float s = 0.f;
        for (int mm = 0; mm < nm; mm++) s = fmaf(cg[mm], y[mm], s);
        Dsh[gf][e] = s * Nsh[gf][bij];
    }
    __syncthreads();

    // warp-pure compute mapping: tid -> (j, g, column c, v, jo)
    int j, g, c, v, jo;
    if (tid < 160) {            // j = 2 : 80 columns per z (c = 64..143)
        j = 2; g = tid / 80;
        int x = tid - 80 * g;
        c = 64 + x; v = x / 5; jo = x - 5 * v;
    } else if (tid < 256) {     // j = 1 : 48 columns per z (c = 16..63)
        j = 1;
        int x = tid - 160; g = x / 48; x -= 48 * g;
        c = 16 + x; v = x / 3; jo = x - 3 * v;
    } else {                    // j = 0 : 16 columns per z (c = 0..15)
        j = 0;
        int x = tid - 256; g = x / 16; x -= 16 * g;
        c = x; v = x; jo = 0;
    }

    const int z = blockIdx.x * 2 + g;
    const float* Rz = R + (size_t)z * NPATH;
    float* op = out + (size_t)z * (OUTD * OUTD) + c;
    if (j == 0)      compute_cols0(Rz, Dsh[g], op, v);
    else if (j == 1) compute_cols<1>(Rz, Rsh[g], Dsh[g], op, v, jo);
    else             compute_cols<2>(Rz, Rsh[g], Dsh[g], op, v, jo);
}

extern "C" void kernel_launch(void* const* d_in, const int* in_sizes, int n_in,
                              void* d_out, int out_size) {
    const float* Y  = (const float*)d_in[0];
    const float* R  = (const float*)d_in[1];
    const float* NC = (const float*)d_in[2];
    float* out = (float*)d_out;
    int batch = in_sizes[0] / YDIM;       // 4096
    tp_kernel<<<batch / 2, 288>>>(Y, R, NC, out, batch);
}

// round 16
// speedup vs baseline: 1.9130x; 1.9130x over previous
#include <cuda_runtime.h>
#include <math.h>

#define YDIM  25
#define NPATH 4864
#define OUTD  144
#define DTOT  259
#define SRTOT 3584   // staged R floats per z (bij 4,5,7,8 only)

// runtime-indexed metadata (used in D-build phase)
__constant__ int c_NLF[9]   = {1,1,1,1,3,3,1,3,5};
__constant__ int c_DBASE[9] = {0,1,4,9,12,39,84,89,134};
__constant__ int c_LF0[9]   = {0,1,2,1,0,1,2,1,0};
__constant__ int c_CGB[9][5] = {
    {0,0,0,0,0},{1,0,0,0,0},{10,0,0,0,0},{35,0,0,0,0},
    {44,53,80,0,0},{125,170,245,0,0},{350,0,0,0,0},
    {375,420,495,0,0},{600,625,700,825,1000}};
__constant__ int c_YOFF[5]  = {0,1,4,9,16};

// compile-time metadata
__host__ __device__ constexpr int K_ROFF[9]  = {0,256,512,768,1024,1792,2560,2816,3584};
__host__ __device__ constexpr int K_DBASE[9] = {0,1,4,9,12,39,84,89,134};
// smem float offsets for staged bij blocks (4,5,7,8); others unstaged (LDG16)
__host__ __device__ constexpr int K_SOFF[9]  = {-1,-1,-1,-1,0,768,-1,1536,2304};

// ---------------------------------------------------------------------------
// Compile-time CG table (constexpr fp64 Wigner-3j + basis transform)
// ---------------------------------------------------------------------------
struct CGTable { float v[1225]; };
struct CCd { double re, im; };

constexpr double cfact(int n) { double f = 1.0; for (int i = 2; i <= n; ++i) f *= (double)i; return f; }

constexpr double csqrt_(double x) {
    if (x <= 0.0) return 0.0;
    double g = (x > 1.0) ? x : 1.0;
    for (int i = 0; i < 80; ++i) g = 0.5 * (g + x / g);
    return g;
}

constexpr double cw3j(int j1, int j2, int j3, int m1, int m2, int m3) {
    if (m1 + m2 + m3 != 0) return 0.0;
    int dj = (j1 > j2) ? (j1 - j2) : (j2 - j1);
    if (j3 < dj || j3 > j1 + j2) return 0.0;
    int am1 = m1 < 0 ? -m1 : m1, am2 = m2 < 0 ? -m2 : m2, am3 = m3 < 0 ? -m3 : m3;
    if (am1 > j1 || am2 > j2 || am3 > j3) return 0.0;
    double pre = csqrt_(cfact(j1+j2-j3)*cfact(j1-j2+j3)*cfact(-j1+j2+j3)/cfact(j1+j2+j3+1));
    pre *= csqrt_(cfact(j1+m1)*cfact(j1-m1)*cfact(j2+m2)*cfact(j2-m2)*cfact(j3+m3)*cfact(j3-m3));
    int t0 = 0;
    if (j2 - j3 - m1 > t0) t0 = j2 - j3 - m1;
    if (j1 - j3 + m2 > t0) t0 = j1 - j3 + m2;
    int t1 = j1 + j2 - j3;
    if (j1 - m1 < t1) t1 = j1 - m1;
    if (j2 + m2 < t1) t1 = j2 + m2;
    double s = 0.0;
    for (int t = t0; t <= t1; ++t) {
        double d = cfact(t)*cfact(j3-j2+m1+t)*cfact(j3-j1-m2+t)
                 * cfact(j1+j2-j3-t)*cfact(j1-m1-t)*cfact(j2+m2-t);
        s += ((t & 1) ? -1.0 : 1.0) / d;
    }
    int p = j1 - j2 - m3;
    double sg = (p & 1) ? -1.0 : 1.0;
    return sg * pre * s;
}

constexpr CCd aent(int l, int r, int c) {
    CCd o{0.0, 0.0};
    int M = r - l, m = c - l;
    double s2 = csqrt_(0.5);
    if (M > 0) {
        double sg = (M & 1) ? -s2 : s2;
        if (m == M)       o.re = sg;
        else if (m == -M) o.im = sg;
    } else if (M < 0) {
        if (m == -M)      o.re = s2;
        else if (m == M)  o.im = -s2;
    } else {
        if (m == 0) o.re = 1.0;
    }
    return o;
}

constexpr CGTable makeCG() {
    CGTable T{};
    int CGB[9][5] = {
        {0,0,0,0,0},{1,0,0,0,0},{10,0,0,0,0},{35,0,0,0,0},
        {44,53,80,0,0},{125,170,245,0,0},{350,0,0,0,0},
        {375,420,495,0,0},{600,625,700,825,1000}};
    for (int bij = 0; bij < 9; ++bij) {
        int l1 = bij / 3, l2 = bij % 3;
        int dl = (l1 > l2) ? (l1 - l2) : (l2 - l1);
        int nk = 2 * ((l1 < l2) ? l1 : l2) + 1;
        for (int k = 0; k < nk; ++k) {
            int l3 = dl + k;
            int n1 = 2*l1+1, n2 = 2*l2+1, n3 = 2*l3+1;
            double Cre[225] = {}, Cim[225] = {};
            for (int m1 = -l1; m1 <= l1; ++m1)
                for (int m2 = -l2; m2 <= l2; ++m2) {
                    int m3 = -(m1 + m2);
                    if (m3 < -l3 || m3 > l3) continue;
                    double w = cw3j(l1, l2, l3, m1, m2, m3);
                    if (w == 0.0) continue;
                    for (int i = 0; i < n1; ++i) {
                        CCd a1 = aent(l1, m1 + l1, i); a1.im = -a1.im;
                        for (int j = 0; j < n2; ++j) {
                            CCd a2 = aent(l2, m2 + l2, j); a2.im = -a2.im;
                            double pr = a1.re*a2.re - a1.im*a2.im;
                            double pi = a1.re*a2.im + a1.im*a2.re;
                            for (int kk = 0; kk < n3; ++kk) {
                                CCd a3 = aent(l3, m3 + l3, kk); a3.im = -a3.im;
                                double qr = pr*a3.re - pi*a3.im;
                                double qi = pr*a3.im + pi*a3.re;
                                int x = (i*n2 + j)*n3 + kk;
                                Cre[x] += w * qr;
                                Cim[x] += w * qi;
                            }
                        }
                    }
                }
            int tot = n1 * n2 * n3;
            double nr = 0.0, ni = 0.0;
            for (int x = 0; x < tot; ++x) { nr += Cre[x]*Cre[x]; ni += Cim[x]*Cim[x]; }
            bool useRe = (nr >= ni);
            double nn = csqrt_(useRe ? nr : ni);
            int base = CGB[bij][k];
            for (int x = 0; x < tot; ++x) {
                double vl = useRe ? Cre[x] : Cim[x];
                T.v[base + x] = (float)((nn > 0.0) ? vl / nn : 0.0);
            }
        }
    }
    return T;
}

constexpr CGTable CGT = makeCG();
__device__ const CGTable d_CGT = CGT;

// ---------------------------------------------------------------------------
// Main kernel (R14 configuration — empirical optimum).
// 288 threads = 2 z; warp-pure j mapping; single-column ownership.
// NLF=1 sub-blocks (bij 0,1,2,3,6): batched MLP=16 LDG prefetch into registers
// then pure stores. NLF>1 sub-blocks (bij 4,5,7,8): smem-staged, D hoisted to
// registers with NIO=5 split into io-chunks of 3+2 (worst-path hoist 15 regs).
// u-loops at unroll 4 — the batching depth that fits the 32-reg budget.
// smem ~30KB + regs<=32 -> 7 blocks/SM = 63 warps (1 below the 64-warp cap).
// ---------------------------------------------------------------------------
template<int NC_, int NSTRIDE, int NLF, int NJI>
__device__ __forceinline__ void do_iblock(const float* __restrict__ Sg, int rb,
                                          const float* __restrict__ dpb,
                                          float* __restrict__ op)
{
    float D[NC_ * NLF];
    #pragma unroll
    for (int io = 0; io < NC_; io++)
        #pragma unroll
        for (int k = 0; k < NLF; k++)
            D[io*NLF + k] = dpb[io * (NJI*NLF) + k];

    #pragma unroll 4
    for (int u = 0; u < 16; u++) {
        float rv[NLF];
        #pragma unroll
        for (int k = 0; k < NLF; k++) rv[k] = Sg[rb + k];
        float* o = op;
        #pragma unroll
        for (int io = 0; io < NC_; io++) {
            float acc = 0.f;
            #pragma unroll
            for (int k = 0; k < NLF; k++) acc = fmaf(D[io*NLF + k], rv[k], acc);
            __stcs(o, acc);
            o += OUTD;
        }
        rb += 16 * NLF;
        op += NSTRIDE * OUTD;
    }
}

// NLF=1 path: prefetch all 16 R scalars (independent LDGs), then pure stores.
template<int NIO, int NJI>
__device__ __forceinline__ void iblk_ldg16(const float* __restrict__ rp,
                                           const float* __restrict__ dpb,
                                           float* __restrict__ op)
{
    float rv[16];
    #pragma unroll
    for (int u = 0; u < 16; u++) rv[u] = __ldg(rp + u*16);
    float D[NIO];
    #pragma unroll
    for (int io = 0; io < NIO; io++) D[io] = dpb[io*NJI];
    #pragma unroll 4
    for (int u = 0; u < 16; u++) {
        float* o = op + (size_t)(u * NIO) * OUTD;
        #pragma unroll
        for (int io = 0; io < NIO; io++) {
            __stcs(o, D[io] * rv[u]);
            o += OUTD;
        }
    }
}

template<int LJ>
__device__ __forceinline__ void compute_cols(const float* __restrict__ Rz,
                                             const float* __restrict__ Sg,
                                             const float* __restrict__ Dg,
                                             float* __restrict__ op,
                                             int v, int jo)
{
    constexpr int NJI = 2*LJ + 1;
    // i = 0  (bij = LJ, NLF = 1, unstaged -> LDG16 prefetch)
    iblk_ldg16<1, NJI>(Rz + K_ROFF[LJ] + v, Dg + K_DBASE[LJ] + jo, op);
    // i = 1  (bij = 3+LJ, NIO = 3, staged, NLF = 3)
    do_iblock<3, 3, 3, NJI>(Sg, K_SOFF[3+LJ] + v*3,
                            Dg + K_DBASE[3+LJ] + jo*3, op + 16*OUTD);
    // i = 2  (bij = 6+LJ, NIO = 5, staged) -> io-chunks 3 + 2
    {
        constexpr int NLF = (LJ == 1) ? 3 : 5;
        const float* dpb = Dg + K_DBASE[6+LJ] + jo*NLF;
        const int rb = K_SOFF[6+LJ] + v*NLF;
        do_iblock<3, 5, NLF, NJI>(Sg, rb, dpb, op + 64*OUTD);
        do_iblock<2, 5, NLF, NJI>(Sg, rb, dpb + 3*(NJI*NLF),
                                  op + 64*OUTD + 3*OUTD);
    }
}

__device__ __forceinline__ void compute_cols0(const float* __restrict__ Rz,
                                              const float* __restrict__ Dg,
                                              float* __restrict__ op, int v)
{
    iblk_ldg16<1, 1>(Rz + K_ROFF[0] + v, Dg + K_DBASE[0], op);
    iblk_ldg16<3, 1>(Rz + K_ROFF[3] + v, Dg + K_DBASE[3], op + 16*OUTD);
    iblk_ldg16<5, 1>(Rz + K_ROFF[6] + v, Dg + K_DBASE[6], op + 64*OUTD);
}

__global__ __launch_bounds__(288, 7)
void tp_kernel(const float* __restrict__ Y, const float* __restrict__ R,
               const float* __restrict__ NC, float* __restrict__ out, int batch)
{
    __shared__ float Rsh[2][SRTOT];
    __shared__ float Ysh[2][YDIM];
    __shared__ float Nsh[2][9];
    __shared__ float Dsh[2][DTOT];

    const int tid = threadIdx.x;
    const int gf = tid / 144;
    const int cf = tid - gf * 144;

    // stage bij {4,5} and {7,8} R segments -> smem, 16B vectors, streaming
    {
        const int zf = blockIdx.x * 2 + gf;
        const float4* Rz4 = (const float4*)(R + (size_t)zf * NPATH);
        float4* S4 = (float4*)Rsh[gf];
        // floats [1024,2560) -> 0 ; [2816,4864) -> 1536
        for (int idx = cf; idx < 384; idx += 144) S4[idx]       = __ldcs(Rz4 + 256 + idx);
        for (int idx = cf; idx < 512; idx += 144) S4[384 + idx] = __ldcs(Rz4 + 704 + idx);
        if (cf < YDIM) Ysh[gf][cf] = Y[cf * batch + zf];
        if (cf < 9)    Nsh[gf][cf] = NC[cf * batch + zf];
    }
    __syncthreads();

    // D[e] = norm[bij] * sum_m CG[bij,k][pair][m] * Y[yoff+m]   (259 entries)
    for (int e = cf; e < DTOT; e += 144) {
        int bij = (e>=134)?8:(e>=89)?7:(e>=84)?6:(e>=39)?5:(e>=12)?4:(e>=9)?3:(e>=4)?2:(e>=1)?1:0;
        int local = e - c_DBASE[bij];
        int nlf = c_NLF[bij];
        int k = local % nlf;
        int pair = local / nlf;
        int lf = c_LF0[bij] + k;
        int nm = 2*lf + 1;
        const float* cg = d_CGT.v + c_CGB[bij][k] + pair * nm;
        const float* y  = Ysh[gf] + c_YOFF[lf];
        float s = 0.f;
        for (int mm = 0; mm < nm; mm++) s = fmaf(cg[mm], y[mm], s);
        Dsh[gf][e] = s * Nsh[gf][bij];
    }
    __syncthreads();

    // warp-pure compute mapping: tid -> (j, g, column c, v, jo)
    int j, g, c, v, jo;
    if (tid < 160) {            // j = 2 : 80 columns per z (c = 64..143)
        j = 2; g = tid / 80;
        int x = tid - 80 * g;
        c = 64 + x; v = x / 5; jo = x - 5 * v;
    } else if (tid < 256) {     // j = 1 : 48 columns per z (c = 16..63)
        j = 1;
        int x = tid - 160; g = x / 48; x -= 48 * g;
        c = 16 + x; v = x / 3; jo = x - 3 * v;
    } else {                    // j = 0 : 16 columns per z (c = 0..15)
        j = 0;
        int x = tid - 256; g = x / 16; x -= 16 * g;
        c = x; v = x; jo = 0;
    }

    const int z = blockIdx.x * 2 + g;
    const float* Rz = R + (size_t)z * NPATH;
    float* op = out + (size_t)z * (OUTD * OUTD) + c;
    if (j == 0)      compute_cols0(Rz, Dsh[g], op, v);
    else if (j == 1) compute_cols<1>(Rz, Rsh[g], Dsh[g], op, v, jo);
    else             compute_cols<2>(Rz, Rsh[g], Dsh[g], op, v, jo);
}

extern "C" void kernel_launch(void* const* d_in, const int* in_sizes, int n_in,
                              void* d_out, int out_size) {
    const float* Y  = (const float*)d_in[0];
    const float* R  = (const float*)d_in[1];
    const float* NC = (const float*)d_in[2];
    float* out = (float*)d_out;
    int batch = in_sizes[0] / YDIM;       // 4096
    tp_kernel<<<batch / 2, 288>>>(Y, R, NC, out, batch);
}